// round 10
// baseline (speedup 1.0000x reference)
#include <cuda_runtime.h>
#include <cstdint>

// IOVPreTrainedEmbeddings: out[b,s,:] = (oov_map[x[b,s]] >= 0)
//                                         ? oov_embed[oov_map[x[b,s]], :]
//                                         : w2v[x[b,s], :]
//
// x [131072] i32, w2v [100000,300] f32, oov_embed [5000,300] f32,
// oov_map [100000] i32, out [131072,300] f32.
//
// R9: PARTIAL L2 pinning. R7 (pin-everything) gained only ~2us wall:
// hypothesis = 88MB+ of evict_last lines self-thrash in the protected ways
// of the 126MB L2. Pin only w2v rows < 60000 (~72MB) + oov_embed (6MB);
// stream the rest with evict_first. Protected set now fits -> survives
// across graph replays -> steady-state DRAM reads drop ~74MB -> ~35MB.
// Stores remain evict-first (__stcs). Loads/stores in separate phases to
// avoid volatile-asm ld/st interleave serializing the chain.

static constexpr int TOKENS   = 128 * 1024;   // B*S
static constexpr int DIM      = 300;
static constexpr int VEC      = DIM / 4;      // 75 float4 per row (1200B stride)
static constexpr long long TOTAL4 = (long long)TOKENS * VEC;  // 9,830,400
static constexpr int PIN_ROWS = 60000;        // w2v rows pinned in L2 (~72MB)

static constexpr int THREADS = 256;
static constexpr int UNROLL  = 8;
static constexpr int BLOCKS  = (int)(TOTAL4 / ((long long)THREADS * UNROLL)); // 4800, exact
static constexpr int STRIDE  = THREADS * BLOCKS;  // 1,228,800

__device__ __forceinline__ uint64_t policy_evict_last() {
    uint64_t pol;
    asm("createpolicy.fractional.L2::evict_last.b64 %0, 1.0;" : "=l"(pol));
    return pol;
}
__device__ __forceinline__ uint64_t policy_evict_first() {
    uint64_t pol;
    asm("createpolicy.fractional.L2::evict_first.b64 %0, 1.0;" : "=l"(pol));
    return pol;
}

__device__ __forceinline__ int ldg_i32_pol(const int* p, uint64_t pol) {
    int v;
    asm volatile("ld.global.nc.L2::cache_hint.b32 %0, [%1], %2;"
                 : "=r"(v) : "l"(p), "l"(pol));
    return v;
}

__device__ __forceinline__ float4 ldg_f4_pol(const float4* p, uint64_t pol) {
    float4 v;
    asm volatile("ld.global.nc.L2::cache_hint.v4.f32 {%0,%1,%2,%3}, [%4], %5;"
                 : "=f"(v.x), "=f"(v.y), "=f"(v.z), "=f"(v.w)
                 : "l"(p), "l"(pol));
    return v;
}

__global__ __launch_bounds__(THREADS)
void iov_gather_ppin_kernel(const int*    __restrict__ x,
                            const float4* __restrict__ w2v,       // row stride VEC
                            const float4* __restrict__ oov_embed, // row stride VEC
                            const int*    __restrict__ oov_map,
                            float4*       __restrict__ out)
{
    const int base = blockIdx.x * THREADS + threadIdx.x;
    const uint64_t pol_last  = policy_evict_last();
    const uint64_t pol_first = policy_evict_first();

    int id[UNROLL];
    int row[UNROLL];
    float4 val[UNROLL];

    // Phase 1: token ids (small tables, pin).
    #pragma unroll
    for (int k = 0; k < UNROLL; k++) {
        int token = (base + k * STRIDE) / VEC;   // mul-shift div by 75
        id[k] = ldg_i32_pol(&x[token], pol_last);
    }

    // Phase 2: oov_map gathers (400KB, pin).
    #pragma unroll
    for (int k = 0; k < UNROLL; k++)
        row[k] = ldg_i32_pol(&oov_map[id[k]], pol_last);

    // Phase 3: payload gathers. Pin oov rows + w2v rows < PIN_ROWS;
    // stream the rest with evict_first so they never displace the
    // protected set.
    #pragma unroll
    for (int k = 0; k < UNROLL; k++) {
        int i     = base + k * STRIDE;
        int token = i / VEC;
        int chunk = i - token * VEC;
        bool is_oov = (row[k] >= 0);
        const float4* src = is_oov
            ? (oov_embed + (long long)row[k] * VEC + chunk)
            : (w2v       + (long long)id[k]  * VEC + chunk);
        uint64_t pol = (is_oov || id[k] < PIN_ROWS) ? pol_last : pol_first;
        val[k] = ldg_f4_pol(src, pol);
    }

    // Phase 4: evict-first streaming stores.
    #pragma unroll
    for (int k = 0; k < UNROLL; k++)
        __stcs(&out[base + k * STRIDE], val[k]);
}

extern "C" void kernel_launch(void* const* d_in, const int* in_sizes, int n_in,
                              void* d_out, int out_size)
{
    const int*    x         = (const int*)   d_in[0];
    const float4* w2v       = (const float4*)d_in[1];
    const float4* oov_embed = (const float4*)d_in[2];
    const int*    oov_map   = (const int*)   d_in[3];
    float4*       out       = (float4*)d_out;

    iov_gather_ppin_kernel<<<BLOCKS, THREADS>>>(x, w2v, oov_embed, oov_map, out);
}

// round 11
// speedup vs baseline: 1.0321x; 1.0321x over previous
#include <cuda_runtime.h>
#include <cstdint>

// IOVPreTrainedEmbeddings: out[b,s,:] = (oov_map[x[b,s]] >= 0)
//                                         ? oov_embed[oov_map[x[b,s]], :]
//                                         : w2v[x[b,s], :]
//
// x [131072] i32, w2v [100000,300] f32, oov_embed [5000,300] f32,
// oov_map [100000] i32, out [131072,300] f32.
//
// R10: statistical partial pinning. R9's explicit id-threshold pinning
// regressed purely from register pressure (48 regs, occ 51%). Same idea
// at zero cost: createpolicy.fractional evict_last with fraction 0.5 tags
// ~half the payload lines protected (~50MB pinned set fits the protected
// ways and survives the 157MB/launch write stream across graph replays),
// no branches, no extra registers. Index tables pinned at fraction 1.0
// (tiny). Stores stay evict-first (__stcs). Body identical to R7 (32 regs,
// occ ~82%).

static constexpr int TOKENS = 128 * 1024;     // B*S
static constexpr int DIM    = 300;
static constexpr int VEC    = DIM / 4;        // 75 float4 per row (1200B stride)
static constexpr long long TOTAL4 = (long long)TOKENS * VEC;  // 9,830,400

static constexpr int THREADS = 256;
static constexpr int UNROLL  = 8;
static constexpr int BLOCKS  = (int)(TOTAL4 / ((long long)THREADS * UNROLL)); // 4800, exact
static constexpr int STRIDE  = THREADS * BLOCKS;  // 1,228,800

__device__ __forceinline__ uint64_t policy_evict_last_full() {
    uint64_t pol;
    asm("createpolicy.fractional.L2::evict_last.b64 %0, 1.0;" : "=l"(pol));
    return pol;
}
__device__ __forceinline__ uint64_t policy_evict_last_half() {
    uint64_t pol;
    asm("createpolicy.fractional.L2::evict_last.b64 %0, 0.5;" : "=l"(pol));
    return pol;
}

__device__ __forceinline__ int ldg_i32_pol(const int* p, uint64_t pol) {
    int v;
    asm volatile("ld.global.nc.L2::cache_hint.b32 %0, [%1], %2;"
                 : "=r"(v) : "l"(p), "l"(pol));
    return v;
}

__device__ __forceinline__ float4 ldg_f4_pol(const float4* p, uint64_t pol) {
    float4 v;
    asm volatile("ld.global.nc.L2::cache_hint.v4.f32 {%0,%1,%2,%3}, [%4], %5;"
                 : "=f"(v.x), "=f"(v.y), "=f"(v.z), "=f"(v.w)
                 : "l"(p), "l"(pol));
    return v;
}

__global__ __launch_bounds__(THREADS)
void iov_gather_frac_kernel(const int*    __restrict__ x,
                            const float4* __restrict__ w2v,       // row stride VEC
                            const float4* __restrict__ oov_embed, // row stride VEC
                            const int*    __restrict__ oov_map,
                            float4*       __restrict__ out)
{
    const int base = blockIdx.x * THREADS + threadIdx.x;
    const uint64_t pol_idx = policy_evict_last_full();   // tiny index tables
    const uint64_t pol_pay = policy_evict_last_half();   // ~50% of table lines protected

    int id[UNROLL];
    int row[UNROLL];

    // Phase 1: token ids.
    #pragma unroll
    for (int k = 0; k < UNROLL; k++) {
        int token = (base + k * STRIDE) / VEC;   // mul-shift div by 75
        id[k] = ldg_i32_pol(&x[token], pol_idx);
    }

    // Phase 2: oov_map gathers (400KB, pinned).
    #pragma unroll
    for (int k = 0; k < UNROLL; k++)
        row[k] = ldg_i32_pol(&oov_map[id[k]], pol_idx);

    // Phase 3+4: payload gather (half-pinned) + evict-first streaming store.
    #pragma unroll
    for (int k = 0; k < UNROLL; k++) {
        int i     = base + k * STRIDE;
        int token = i / VEC;
        int chunk = i - token * VEC;
        const float4* src = (row[k] >= 0)
            ? (oov_embed + (long long)row[k] * VEC + chunk)
            : (w2v       + (long long)id[k]  * VEC + chunk);
        float4 v = ldg_f4_pol(src, pol_pay);
        __stcs(&out[i], v);
    }
}

extern "C" void kernel_launch(void* const* d_in, const int* in_sizes, int n_in,
                              void* d_out, int out_size)
{
    const int*    x         = (const int*)   d_in[0];
    const float4* w2v       = (const float4*)d_in[1];
    const float4* oov_embed = (const float4*)d_in[2];
    const int*    oov_map   = (const int*)   d_in[3];
    float4*       out       = (float4*)d_out;

    iov_gather_frac_kernel<<<BLOCKS, THREADS>>>(x, w2v, oov_embed, oov_map, out);
}